// round 1
// baseline (speedup 1.0000x reference)
#include <cuda_runtime.h>
#include <cuda_bf16.h>
#include <math.h>

#define N_NODES 100000
#define N_EDGES 600000
#define HID 128

// ---------------- device scratch (no allocs allowed) ----------------
__device__ float g_H[(size_t)N_NODES * HID];   // h = X @ W
__device__ float g_A[(size_t)N_NODES * HID];   // accumulator / layer output (pre-activation)
__device__ float g_dinv[N_NODES];              // rsqrt(deg)
__device__ float g_recip[N_NODES];             // 1/deg
__device__ int   g_cnt[N_NODES];               // in-degree count
__device__ float g_gate[HID];                  // temporal gate
__device__ int   g_is64;                       // edge_index dtype flag

// ---------------- edge-index dtype detection ----------------
// If edge_index is int64 (little-endian), every odd int32 word is 0 (values < 2^31).
// If int32, odd words are random node ids in [0,1e5) -> essentially surely nonzero.
__global__ void detect_kernel(const int* __restrict__ ei) {
    __shared__ int any_nz;
    if (threadIdx.x == 0) any_nz = 0;
    __syncthreads();
    int local = 0;
    for (int i = threadIdx.x; i < 4096; i += blockDim.x) {
        local |= ei[2 * i + 1];
    }
    if (local) atomicOr(&any_nz, 1);
    __syncthreads();
    if (threadIdx.x == 0) g_is64 = (any_nz == 0) ? 1 : 0;
}

__device__ __forceinline__ int edge_src(const int* ei, int e, int is64) {
    return is64 ? ei[2 * e] : ei[e];
}
__device__ __forceinline__ int edge_dst(const int* ei, int e, int is64) {
    return is64 ? ei[2 * (N_EDGES + e)] : ei[N_EDGES + e];
}

// ---------------- degree ----------------
__global__ void zero_cnt_kernel() {
    int i = blockIdx.x * blockDim.x + threadIdx.x;
    if (i < N_NODES) g_cnt[i] = 0;
}

__global__ void count_kernel(const int* __restrict__ ei) {
    int e = blockIdx.x * blockDim.x + threadIdx.x;
    if (e >= N_EDGES) return;
    int is64 = g_is64;
    int d = edge_dst(ei, e, is64);
    atomicAdd(&g_cnt[d], 1);
}

__global__ void finalize_deg_kernel() {
    int i = blockIdx.x * blockDim.x + threadIdx.x;
    if (i >= N_NODES) return;
    float deg = (float)g_cnt[i] + 1.0f;
    g_dinv[i]  = rsqrtf(deg);
    g_recip[i] = 1.0f / deg;
}

// ---------------- temporal gate: sigmoid(tanh(t*Wg1+bg1) @ Wg2 + bg2) ----------------
__global__ void gate_kernel(const float* __restrict__ t,
                            const float* __restrict__ Wg1, const float* __restrict__ bg1,
                            const float* __restrict__ Wg2, const float* __restrict__ bg2) {
    __shared__ float h1[HID];
    int j = threadIdx.x;
    float tv = t[0];
    h1[j] = tanhf(tv * Wg1[j] + bg1[j]);
    __syncthreads();
    float s = bg2[j];
#pragma unroll 8
    for (int k = 0; k < HID; k++) s += h1[k] * Wg2[k * HID + j];
    g_gate[j] = 1.0f / (1.0f + expf(-s));
}

// ---------------- GEMM: H = act(Xin) @ W ; A = H*recip + b  ----------------
// Block: 256 threads, 64 rows x 128 cols. Thread: 8 rows x 4 cols.
// act==1: Xin element pass through relu(x)*gate[col] (reads rows this block will
// later overwrite in A -> no cross-block hazard when Xin == A).
__global__ __launch_bounds__(256) void gemm_kernel(
    const float* __restrict__ Xin, const float* __restrict__ W,
    const float* __restrict__ b, float* __restrict__ H,
    float* __restrict__ A, int act) {
    extern __shared__ float sm[];
    float* Ws = sm;            // 128*128
    float* Xs = sm + 16384;    // 64*128

    int tx = threadIdx.x;
    int row0 = blockIdx.x * 64;

    // load W (K-major [k][j]) into smem
#pragma unroll 4
    for (int i = tx; i < 4096; i += 256)
        ((float4*)Ws)[i] = ((const float4*)W)[i];

    // load X tile (64 x 128), optional fused relu*gate
#pragma unroll
    for (int i = tx; i < 2048; i += 256) {
        int r = i >> 5;
        int c4 = i & 31;
        int row = row0 + r;
        float4 v = make_float4(0.f, 0.f, 0.f, 0.f);
        if (row < N_NODES) {
            v = ((const float4*)(Xin + (size_t)row * HID))[c4];
            if (act) {
                float4 g = ((const float4*)g_gate)[c4];
                v.x = fmaxf(v.x, 0.f) * g.x;
                v.y = fmaxf(v.y, 0.f) * g.y;
                v.z = fmaxf(v.z, 0.f) * g.z;
                v.w = fmaxf(v.w, 0.f) * g.w;
            }
        }
        ((float4*)(Xs + r * HID))[c4] = v;
    }
    __syncthreads();

    int j0 = (tx & 31) * 4;    // 4 consecutive output cols
    int rg = (tx >> 5) * 8;    // 8 rows

    float4 acc[8];
#pragma unroll
    for (int r = 0; r < 8; r++) acc[r] = make_float4(0.f, 0.f, 0.f, 0.f);

#pragma unroll 4
    for (int k = 0; k < HID; k++) {
        float4 wv = *(const float4*)(Ws + k * HID + j0);
#pragma unroll
        for (int r = 0; r < 8; r++) {
            float xv = Xs[(rg + r) * HID + k];   // broadcast within warp
            acc[r].x += xv * wv.x;
            acc[r].y += xv * wv.y;
            acc[r].z += xv * wv.z;
            acc[r].w += xv * wv.w;
        }
    }

    float4 bv = *(const float4*)(b + j0);
#pragma unroll
    for (int r = 0; r < 8; r++) {
        int row = row0 + rg + r;
        if (row < N_NODES) {
            float rc = g_recip[row];
            *(float4*)(H + (size_t)row * HID + j0) = acc[r];
            float4 o;
            o.x = acc[r].x * rc + bv.x;
            o.y = acc[r].y * rc + bv.y;
            o.z = acc[r].z * rc + bv.z;
            o.w = acc[r].w * rc + bv.w;
            *(float4*)(A + (size_t)row * HID + j0) = o;
        }
    }
}

// ---------------- scatter: A[dst] += H[src] * dinv[src]*dinv[dst] ----------------
// one warp per edge; one red.global.add.v4.f32 per lane (128 floats/row)
__global__ __launch_bounds__(256) void scatter_kernel(const int* __restrict__ ei,
                                                      const float* __restrict__ H,
                                                      float* __restrict__ A) {
    int gtid = blockIdx.x * blockDim.x + threadIdx.x;
    int e = gtid >> 5;
    int lane = threadIdx.x & 31;
    if (e >= N_EDGES) return;
    int is64 = g_is64;
    int s = edge_src(ei, e, is64);
    int d = edge_dst(ei, e, is64);
    float w = g_dinv[s] * g_dinv[d];
    float4 hv = ((const float4*)(H + (size_t)s * HID))[lane];
    float4 m = make_float4(hv.x * w, hv.y * w, hv.z * w, hv.w * w);
    float* dst = A + (size_t)d * HID + lane * 4;
    asm volatile("red.global.add.v4.f32 [%0], {%1,%2,%3,%4};"
                 :: "l"(dst), "f"(m.x), "f"(m.y), "f"(m.z), "f"(m.w)
                 : "memory");
}

// ---------------- final activation: out = relu(A) * gate ----------------
__global__ void act_out_kernel(const float* __restrict__ A, float* __restrict__ out) {
    int i = blockIdx.x * blockDim.x + threadIdx.x;  // float4 index
    if (i >= N_NODES * HID / 4) return;
    int c4 = i & 31;
    float4 g = ((const float4*)g_gate)[c4];
    float4 v = ((const float4*)A)[i];
    v.x = fmaxf(v.x, 0.f) * g.x;
    v.y = fmaxf(v.y, 0.f) * g.y;
    v.z = fmaxf(v.z, 0.f) * g.z;
    v.w = fmaxf(v.w, 0.f) * g.w;
    ((float4*)out)[i] = v;
}

// ---------------- launch ----------------
extern "C" void kernel_launch(void* const* d_in, const int* in_sizes, int n_in,
                              void* d_out, int out_size) {
    const float* x   = (const float*)d_in[0];
    const int*   ei  = (const int*)d_in[1];    // int32 view; dtype auto-detected
    const float* ts  = (const float*)d_in[2];
    const float* W0  = (const float*)d_in[3];
    const float* b0  = (const float*)d_in[4];
    const float* W1  = (const float*)d_in[5];
    const float* b1  = (const float*)d_in[6];
    const float* W2  = (const float*)d_in[7];
    const float* b2  = (const float*)d_in[8];
    const float* Wg1 = (const float*)d_in[9];
    const float* bg1 = (const float*)d_in[10];
    const float* Wg2 = (const float*)d_in[11];
    const float* bg2 = (const float*)d_in[12];
    float* out = (float*)d_out;

    cudaFuncSetAttribute(gemm_kernel, cudaFuncAttributeMaxDynamicSharedMemorySize, 98304);

    float* H; float* A;
    cudaGetSymbolAddress((void**)&H, g_H);
    cudaGetSymbolAddress((void**)&A, g_A);

    // preprocessing
    detect_kernel<<<1, 256>>>(ei);
    zero_cnt_kernel<<<(N_NODES + 255) / 256, 256>>>();
    count_kernel<<<(N_EDGES + 255) / 256, 256>>>(ei);
    finalize_deg_kernel<<<(N_NODES + 255) / 256, 256>>>();
    gate_kernel<<<1, HID>>>(ts, Wg1, bg1, Wg2, bg2);

    const int gemm_blocks = (N_NODES + 63) / 64;
    const int scat_blocks = (N_EDGES * 32 + 255) / 256;

    // layer 0
    gemm_kernel<<<gemm_blocks, 256, 98304>>>(x, W0, b0, H, A, 0);
    scatter_kernel<<<scat_blocks, 256>>>(ei, H, A);
    // layer 1 (reads A with fused relu*gate, re-inits A)
    gemm_kernel<<<gemm_blocks, 256, 98304>>>(A, W1, b1, H, A, 1);
    scatter_kernel<<<scat_blocks, 256>>>(ei, H, A);
    // layer 2
    gemm_kernel<<<gemm_blocks, 256, 98304>>>(A, W2, b2, H, A, 1);
    scatter_kernel<<<scat_blocks, 256>>>(ei, H, A);
    // final activation
    act_out_kernel<<<(N_NODES * HID / 4 + 255) / 256, 256>>>(A, out);
}

// round 2
// speedup vs baseline: 1.2692x; 1.2692x over previous
#include <cuda_runtime.h>
#include <cuda_bf16.h>
#include <math.h>

#define N_NODES 100000
#define N_EDGES 600000
#define HID 128

typedef unsigned int uint;

// ---------------- device scratch (no allocs allowed) ----------------
__device__ float g_H[(size_t)N_NODES * HID];   // h = X @ W
__device__ float g_A[(size_t)N_NODES * HID];   // accumulator / layer output (pre-activation)
__device__ float g_dinv[N_NODES];              // rsqrt(deg)
__device__ float g_recip[N_NODES];             // 1/deg
__device__ int   g_cnt[N_NODES];               // in-degree count
__device__ float g_gate[HID];                  // temporal gate
__device__ int   g_is64;                       // edge_index dtype flag
__device__ uint  g_Wh[3][8192];                // W hi, fragment-packed bf16x2
__device__ uint  g_Wl[3][8192];                // W lo, fragment-packed bf16x2

// ---------------- edge-index dtype detection ----------------
__global__ void detect_kernel(const int* __restrict__ ei) {
    __shared__ int any_nz;
    if (threadIdx.x == 0) any_nz = 0;
    __syncthreads();
    int local = 0;
    for (int i = threadIdx.x; i < 4096; i += blockDim.x) local |= ei[2 * i + 1];
    if (local) atomicOr(&any_nz, 1);
    __syncthreads();
    if (threadIdx.x == 0) g_is64 = (any_nz == 0) ? 1 : 0;
}

__device__ __forceinline__ int edge_src(const int* ei, int e, int is64) {
    return is64 ? ei[2 * e] : ei[e];
}
__device__ __forceinline__ int edge_dst(const int* ei, int e, int is64) {
    return is64 ? ei[2 * (N_EDGES + e)] : ei[N_EDGES + e];
}

// ---------------- degree ----------------
__global__ void zero_cnt_kernel() {
    int i = blockIdx.x * blockDim.x + threadIdx.x;
    if (i < N_NODES) g_cnt[i] = 0;
}

__global__ void count_kernel(const int* __restrict__ ei) {
    int e = blockIdx.x * blockDim.x + threadIdx.x;
    if (e >= N_EDGES) return;
    atomicAdd(&g_cnt[edge_dst(ei, e, g_is64)], 1);
}

__global__ void finalize_deg_kernel() {
    int i = blockIdx.x * blockDim.x + threadIdx.x;
    if (i >= N_NODES) return;
    float deg = (float)g_cnt[i] + 1.0f;
    g_dinv[i]  = rsqrtf(deg);
    g_recip[i] = 1.0f / deg;
}

// ---------------- temporal gate ----------------
__global__ void gate_kernel(const float* __restrict__ t,
                            const float* __restrict__ Wg1, const float* __restrict__ bg1,
                            const float* __restrict__ Wg2, const float* __restrict__ bg2) {
    __shared__ float h1[HID];
    int j = threadIdx.x;
    float tv = t[0];
    h1[j] = tanhf(tv * Wg1[j] + bg1[j]);
    __syncthreads();
    float s = bg2[j];
#pragma unroll 8
    for (int k = 0; k < HID; k++) s += h1[k] * Wg2[k * HID + j];
    g_gate[j] = 1.0f / (1.0f + expf(-s));
}

// ---------------- W -> fragment-packed bf16 hi/lo ----------------
// Packed index t = ((kc*16+nt)*32 + lane)*2 + r  (uint32 = bf16x2 along k)
// element: W[kc*16 + r*8 + (lane&3)*2 + {0,1}][nt*8 + (lane>>2)]
__global__ void convW_kernel(const float* __restrict__ W,
                             uint* __restrict__ Wh, uint* __restrict__ Wl) {
    int t = blockIdx.x * blockDim.x + threadIdx.x;
    if (t >= 8192) return;
    int r = t & 1, lane = (t >> 1) & 31, nt = (t >> 6) & 15, kc = t >> 10;
    int k = kc * 16 + r * 8 + (lane & 3) * 2;
    int n = nt * 8 + (lane >> 2);
    float w0 = W[k * HID + n];
    float w1 = W[(k + 1) * HID + n];
    __nv_bfloat162 h = __floats2bfloat162_rn(w0, w1);
    __nv_bfloat162 l = __floats2bfloat162_rn(w0 - __bfloat162float(h.x),
                                             w1 - __bfloat162float(h.y));
    Wh[t] = *(uint*)&h;
    Wl[t] = *(uint*)&l;
}

// ---------------- tensor-core GEMM ----------------
__device__ __forceinline__ void mma_bf16(float* c, const uint* a, const uint* b) {
    asm volatile(
        "mma.sync.aligned.m16n8k16.row.col.f32.bf16.bf16.f32 "
        "{%0,%1,%2,%3}, {%4,%5,%6,%7}, {%8,%9}, {%0,%1,%2,%3};"
        : "+f"(c[0]), "+f"(c[1]), "+f"(c[2]), "+f"(c[3])
        : "r"(a[0]), "r"(a[1]), "r"(a[2]), "r"(a[3]), "r"(b[0]), "r"(b[1]));
}

template <int ACT>
__device__ __forceinline__ void load_frag(uint& hi, uint& lo, const float* base,
                                          int k, bool valid, const float* sg) {
    float2 v = valid ? *(const float2*)(base + k) : make_float2(0.f, 0.f);
    if (ACT) {
        v.x = fmaxf(v.x, 0.f) * sg[k];
        v.y = fmaxf(v.y, 0.f) * sg[k + 1];
    }
    __nv_bfloat162 h = __floats2bfloat162_rn(v.x, v.y);
    __nv_bfloat162 l = __floats2bfloat162_rn(v.x - __bfloat162float(h.x),
                                             v.y - __bfloat162float(h.y));
    hi = *(uint*)&h;
    lo = *(uint*)&l;
}

// Block: 256 threads = 8 warps, 128 rows x 128 cols.
// Per warp: 16 rows, 16 n-tiles of 8 cols, K=128 in 8 chunks of 16.
// ACT: input pass through relu(x)*gate (in-place safe: block reads only rows it writes).
// Writes H = acc (pre-norm) and A = acc*recip + b (self-loop + bias, scatter accumulates on top).
template <int ACT>
__global__ __launch_bounds__(256) void gemm_mma_kernel(
    const float* __restrict__ Xin, const uint* __restrict__ Wh,
    const uint* __restrict__ Wl, const float* __restrict__ b,
    float* __restrict__ H, float* __restrict__ A) {
    extern __shared__ uint smem[];
    uint* sWh = smem;                 // 8192
    uint* sWl = smem + 8192;          // 8192
    float* sg = (float*)(smem + 16384);

    int tx = threadIdx.x;
#pragma unroll
    for (int i = tx; i < 2048; i += 256) {
        ((uint4*)sWh)[i] = ((const uint4*)Wh)[i];
        ((uint4*)sWl)[i] = ((const uint4*)Wl)[i];
    }
    if (ACT && tx < HID) sg[tx] = g_gate[tx];
    __syncthreads();

    int warp = tx >> 5, lane = tx & 31;
    int gid = lane >> 2, tig = lane & 3;
    int rg  = blockIdx.x * 128 + warp * 16 + gid;
    int rg8 = rg + 8;
    bool v0 = rg < N_NODES, v8 = rg8 < N_NODES;
    const float* X0 = Xin + (size_t)rg  * HID;
    const float* X8 = Xin + (size_t)rg8 * HID;

    float c[16][4];
#pragma unroll
    for (int nt = 0; nt < 16; nt++)
#pragma unroll
        for (int r = 0; r < 4; r++) c[nt][r] = 0.f;

#pragma unroll
    for (int kc = 0; kc < 8; kc++) {
        int k0 = kc * 16 + tig * 2;
        uint ah[4], al[4];
        load_frag<ACT>(ah[0], al[0], X0, k0,     v0, sg);
        load_frag<ACT>(ah[1], al[1], X8, k0,     v8, sg);
        load_frag<ACT>(ah[2], al[2], X0, k0 + 8, v0, sg);
        load_frag<ACT>(ah[3], al[3], X8, k0 + 8, v8, sg);

        const uint* wh = sWh + (kc * 16) * 64 + lane * 2;
        const uint* wl = sWl + (kc * 16) * 64 + lane * 2;
#pragma unroll
        for (int nt = 0; nt < 16; nt++) {
            uint bh[2], bl[2];
            uint2 t0 = *(const uint2*)(wh + nt * 64);
            uint2 t1 = *(const uint2*)(wl + nt * 64);
            bh[0] = t0.x; bh[1] = t0.y;
            bl[0] = t1.x; bl[1] = t1.y;
            mma_bf16(c[nt], ah, bh);   // hi*hi
            mma_bf16(c[nt], ah, bl);   // hi*lo
            mma_bf16(c[nt], al, bh);   // lo*hi
        }
    }

    float rc0 = v0 ? g_recip[rg]  : 0.f;
    float rc8 = v8 ? g_recip[rg8] : 0.f;
#pragma unroll
    for (int nt = 0; nt < 16; nt++) {
        int col = nt * 8 + tig * 2;
        float2 bb = *(const float2*)(b + col);
        if (v0) {
            *(float2*)(H + (size_t)rg * HID + col) = make_float2(c[nt][0], c[nt][1]);
            *(float2*)(A + (size_t)rg * HID + col) =
                make_float2(c[nt][0] * rc0 + bb.x, c[nt][1] * rc0 + bb.y);
        }
        if (v8) {
            *(float2*)(H + (size_t)rg8 * HID + col) = make_float2(c[nt][2], c[nt][3]);
            *(float2*)(A + (size_t)rg8 * HID + col) =
                make_float2(c[nt][2] * rc8 + bb.x, c[nt][3] * rc8 + bb.y);
        }
    }
}

// ---------------- scatter: A[dst] += H[src] * dinv[src]*dinv[dst] ----------------
__global__ __launch_bounds__(256) void scatter_kernel(const int* __restrict__ ei,
                                                      const float* __restrict__ H,
                                                      float* __restrict__ A) {
    int gtid = blockIdx.x * blockDim.x + threadIdx.x;
    int e = gtid >> 5;
    int lane = threadIdx.x & 31;
    if (e >= N_EDGES) return;
    int is64 = g_is64;
    int s = edge_src(ei, e, is64);
    int d = edge_dst(ei, e, is64);
    float w = g_dinv[s] * g_dinv[d];
    float4 hv = ((const float4*)(H + (size_t)s * HID))[lane];
    float4 m = make_float4(hv.x * w, hv.y * w, hv.z * w, hv.w * w);
    float* dst = A + (size_t)d * HID + lane * 4;
    asm volatile("red.global.add.v4.f32 [%0], {%1,%2,%3,%4};"
                 :: "l"(dst), "f"(m.x), "f"(m.y), "f"(m.z), "f"(m.w)
                 : "memory");
}

// ---------------- final activation ----------------
__global__ void act_out_kernel(const float* __restrict__ A, float* __restrict__ out) {
    int i = blockIdx.x * blockDim.x + threadIdx.x;
    if (i >= N_NODES * HID / 4) return;
    int c4 = i & 31;
    float4 g = ((const float4*)g_gate)[c4];
    float4 v = ((const float4*)A)[i];
    v.x = fmaxf(v.x, 0.f) * g.x;
    v.y = fmaxf(v.y, 0.f) * g.y;
    v.z = fmaxf(v.z, 0.f) * g.z;
    v.w = fmaxf(v.w, 0.f) * g.w;
    ((float4*)out)[i] = v;
}

// ---------------- launch ----------------
extern "C" void kernel_launch(void* const* d_in, const int* in_sizes, int n_in,
                              void* d_out, int out_size) {
    const float* x   = (const float*)d_in[0];
    const int*   ei  = (const int*)d_in[1];
    const float* ts  = (const float*)d_in[2];
    const float* W0  = (const float*)d_in[3];
    const float* b0  = (const float*)d_in[4];
    const float* W1  = (const float*)d_in[5];
    const float* b1  = (const float*)d_in[6];
    const float* W2  = (const float*)d_in[7];
    const float* b2  = (const float*)d_in[8];
    const float* Wg1 = (const float*)d_in[9];
    const float* bg1 = (const float*)d_in[10];
    const float* Wg2 = (const float*)d_in[11];
    const float* bg2 = (const float*)d_in[12];
    float* out = (float*)d_out;

    const int SMEM = 16384 * 4 + 512;
    cudaFuncSetAttribute(gemm_mma_kernel<0>, cudaFuncAttributeMaxDynamicSharedMemorySize, SMEM);
    cudaFuncSetAttribute(gemm_mma_kernel<1>, cudaFuncAttributeMaxDynamicSharedMemorySize, SMEM);

    float *H, *A;
    uint *Wh, *Wl;
    cudaGetSymbolAddress((void**)&H,  g_H);
    cudaGetSymbolAddress((void**)&A,  g_A);
    cudaGetSymbolAddress((void**)&Wh, g_Wh);
    cudaGetSymbolAddress((void**)&Wl, g_Wl);

    // preprocessing
    detect_kernel<<<1, 256>>>(ei);
    zero_cnt_kernel<<<(N_NODES + 255) / 256, 256>>>();
    count_kernel<<<(N_EDGES + 255) / 256, 256>>>(ei);
    finalize_deg_kernel<<<(N_NODES + 255) / 256, 256>>>();
    gate_kernel<<<1, HID>>>(ts, Wg1, bg1, Wg2, bg2);
    convW_kernel<<<32, 256>>>(W0, Wh,            Wl);
    convW_kernel<<<32, 256>>>(W1, Wh + 8192,     Wl + 8192);
    convW_kernel<<<32, 256>>>(W2, Wh + 16384,    Wl + 16384);

    const int gemm_blocks = (N_NODES + 127) / 128;
    const int scat_blocks = (N_EDGES * 32 + 255) / 256;

    // layer 0
    gemm_mma_kernel<0><<<gemm_blocks, 256, SMEM>>>(x, Wh, Wl, b0, H, A);
    scatter_kernel<<<scat_blocks, 256>>>(ei, H, A);
    // layer 1 (fused relu*gate on input, in-place on A)
    gemm_mma_kernel<1><<<gemm_blocks, 256, SMEM>>>(A, Wh + 8192, Wl + 8192, b1, H, A);
    scatter_kernel<<<scat_blocks, 256>>>(ei, H, A);
    // layer 2
    gemm_mma_kernel<1><<<gemm_blocks, 256, SMEM>>>(A, Wh + 16384, Wl + 16384, b2, H, A);
    scatter_kernel<<<scat_blocks, 256>>>(ei, H, A);
    // final activation
    act_out_kernel<<<(N_NODES * HID / 4 + 255) / 256, 256>>>(A, out);
}

// round 3
// speedup vs baseline: 1.2811x; 1.0094x over previous
#include <cuda_runtime.h>
#include <cuda_bf16.h>
#include <math.h>

#define N_NODES 100000
#define N_EDGES 600000
#define HID 128

typedef unsigned int uint;

// ---------------- device scratch (no allocs allowed) ----------------
__device__ float g_H[(size_t)N_NODES * HID];   // h = X @ W
__device__ float g_A[(size_t)N_NODES * HID];   // accumulator / layer output (pre-activation)
__device__ float g_dinv[N_NODES];              // rsqrt(deg)
__device__ float g_recip[N_NODES];             // 1/deg
__device__ int   g_cnt[N_NODES];               // in-degree count
__device__ float g_gate[HID];                  // temporal gate
__device__ int   g_is64;                       // edge_index dtype flag
__device__ uint  g_Wh[3][8192];                // W hi, fragment-packed bf16x2
__device__ uint  g_Wl[3][8192];                // W lo, fragment-packed bf16x2

// ---------------- edge-index dtype detection ----------------
__global__ void detect_kernel(const int* __restrict__ ei) {
    __shared__ int any_nz;
    if (threadIdx.x == 0) any_nz = 0;
    __syncthreads();
    int local = 0;
    for (int i = threadIdx.x; i < 4096; i += blockDim.x) local |= ei[2 * i + 1];
    if (local) atomicOr(&any_nz, 1);
    __syncthreads();
    if (threadIdx.x == 0) g_is64 = (any_nz == 0) ? 1 : 0;
}

__device__ __forceinline__ int edge_src(const int* ei, int e, int is64) {
    return is64 ? ei[2 * e] : ei[e];
}
__device__ __forceinline__ int edge_dst(const int* ei, int e, int is64) {
    return is64 ? ei[2 * (N_EDGES + e)] : ei[N_EDGES + e];
}

// ---------------- degree ----------------
__global__ void zero_cnt_kernel() {
    int i = blockIdx.x * blockDim.x + threadIdx.x;
    if (i < N_NODES) g_cnt[i] = 0;
}

__global__ void count_kernel(const int* __restrict__ ei) {
    int e = blockIdx.x * blockDim.x + threadIdx.x;
    if (e >= N_EDGES) return;
    atomicAdd(&g_cnt[edge_dst(ei, e, g_is64)], 1);
}

__global__ void finalize_deg_kernel() {
    int i = blockIdx.x * blockDim.x + threadIdx.x;
    if (i >= N_NODES) return;
    float deg = (float)g_cnt[i] + 1.0f;
    g_dinv[i]  = rsqrtf(deg);
    g_recip[i] = 1.0f / deg;
}

// ---------------- temporal gate ----------------
__global__ void gate_kernel(const float* __restrict__ t,
                            const float* __restrict__ Wg1, const float* __restrict__ bg1,
                            const float* __restrict__ Wg2, const float* __restrict__ bg2) {
    __shared__ float h1[HID];
    int j = threadIdx.x;
    float tv = t[0];
    h1[j] = tanhf(tv * Wg1[j] + bg1[j]);
    __syncthreads();
    float s = bg2[j];
#pragma unroll 8
    for (int k = 0; k < HID; k++) s += h1[k] * Wg2[k * HID + j];
    g_gate[j] = 1.0f / (1.0f + expf(-s));
}

// ---------------- W -> fragment-packed bf16 hi/lo ----------------
// Packed index t = ((kc*16+nt)*32 + lane)*2 + r  (uint32 = bf16x2 along k)
// element: W[kc*16 + r*8 + (lane&3)*2 + {0,1}][nt*8 + (lane>>2)]
__global__ void convW_kernel(const float* __restrict__ W,
                             uint* __restrict__ Wh, uint* __restrict__ Wl) {
    int t = blockIdx.x * blockDim.x + threadIdx.x;
    if (t >= 8192) return;
    int r = t & 1, lane = (t >> 1) & 31, nt = (t >> 6) & 15, kc = t >> 10;
    int k = kc * 16 + r * 8 + (lane & 3) * 2;
    int n = nt * 8 + (lane >> 2);
    float w0 = W[k * HID + n];
    float w1 = W[(k + 1) * HID + n];
    __nv_bfloat162 h = __floats2bfloat162_rn(w0, w1);
    __nv_bfloat162 l = __floats2bfloat162_rn(w0 - __bfloat162float(h.x),
                                             w1 - __bfloat162float(h.y));
    Wh[t] = *(uint*)&h;
    Wl[t] = *(uint*)&l;
}

// ---------------- tensor-core GEMM ----------------
__device__ __forceinline__ void mma_bf16(float* c, const uint* a, const uint* b) {
    asm volatile(
        "mma.sync.aligned.m16n8k16.row.col.f32.bf16.bf16.f32 "
        "{%0,%1,%2,%3}, {%4,%5,%6,%7}, {%8,%9}, {%0,%1,%2,%3};"
        : "+f"(c[0]), "+f"(c[1]), "+f"(c[2]), "+f"(c[3])
        : "r"(a[0]), "r"(a[1]), "r"(a[2]), "r"(a[3]), "r"(b[0]), "r"(b[1]));
}

template <int ACT>
__device__ __forceinline__ void load_frag(uint& hi, uint& lo, const float* base,
                                          int k, bool valid, const float* sg) {
    float2 v = valid ? *(const float2*)(base + k) : make_float2(0.f, 0.f);
    if (ACT) {
        v.x = fmaxf(v.x, 0.f) * sg[k];
        v.y = fmaxf(v.y, 0.f) * sg[k + 1];
    }
    __nv_bfloat162 h = __floats2bfloat162_rn(v.x, v.y);
    __nv_bfloat162 l = __floats2bfloat162_rn(v.x - __bfloat162float(h.x),
                                             v.y - __bfloat162float(h.y));
    hi = *(uint*)&h;
    lo = *(uint*)&l;
}

// Block: 256 threads = 8 warps, 128 rows x 128 cols.
// Per warp: 16 rows, 16 n-tiles of 8 cols, K=128 in 8 chunks of 16.
// ACT: input pass through relu(x)*gate (in-place safe: block reads only rows it writes).
// Writes H = acc (pre-norm) and A = acc*recip + b (self-loop + bias, scatter accumulates on top).
template <int ACT>
__global__ __launch_bounds__(256) void gemm_mma_kernel(
    const float* __restrict__ Xin, const uint* __restrict__ Wh,
    const uint* __restrict__ Wl, const float* __restrict__ b,
    float* __restrict__ H, float* __restrict__ A) {
    extern __shared__ uint smem[];
    uint* sWh = smem;                 // 8192
    uint* sWl = smem + 8192;          // 8192
    float* sg = (float*)(smem + 16384);

    int tx = threadIdx.x;
#pragma unroll
    for (int i = tx; i < 2048; i += 256) {
        ((uint4*)sWh)[i] = ((const uint4*)Wh)[i];
        ((uint4*)sWl)[i] = ((const uint4*)Wl)[i];
    }
    if (ACT && tx < HID) sg[tx] = g_gate[tx];
    __syncthreads();

    int warp = tx >> 5, lane = tx & 31;
    int gid = lane >> 2, tig = lane & 3;
    int rg  = blockIdx.x * 128 + warp * 16 + gid;
    int rg8 = rg + 8;
    bool v0 = rg < N_NODES, v8 = rg8 < N_NODES;
    const float* X0 = Xin + (size_t)rg  * HID;
    const float* X8 = Xin + (size_t)rg8 * HID;

    float c[16][4];
#pragma unroll
    for (int nt = 0; nt < 16; nt++)
#pragma unroll
        for (int r = 0; r < 4; r++) c[nt][r] = 0.f;

#pragma unroll
    for (int kc = 0; kc < 8; kc++) {
        int k0 = kc * 16 + tig * 2;
        uint ah[4], al[4];
        load_frag<ACT>(ah[0], al[0], X0, k0,     v0, sg);
        load_frag<ACT>(ah[1], al[1], X8, k0,     v8, sg);
        load_frag<ACT>(ah[2], al[2], X0, k0 + 8, v0, sg);
        load_frag<ACT>(ah[3], al[3], X8, k0 + 8, v8, sg);

        const uint* wh = sWh + (kc * 16) * 64 + lane * 2;
        const uint* wl = sWl + (kc * 16) * 64 + lane * 2;
#pragma unroll
        for (int nt = 0; nt < 16; nt++) {
            uint bh[2], bl[2];
            uint2 t0 = *(const uint2*)(wh + nt * 64);
            uint2 t1 = *(const uint2*)(wl + nt * 64);
            bh[0] = t0.x; bh[1] = t0.y;
            bl[0] = t1.x; bl[1] = t1.y;
            mma_bf16(c[nt], ah, bh);   // hi*hi
            mma_bf16(c[nt], ah, bl);   // hi*lo
            mma_bf16(c[nt], al, bh);   // lo*hi
        }
    }

    float rc0 = v0 ? g_recip[rg]  : 0.f;
    float rc8 = v8 ? g_recip[rg8] : 0.f;
#pragma unroll
    for (int nt = 0; nt < 16; nt++) {
        int col = nt * 8 + tig * 2;
        float2 bb = *(const float2*)(b + col);
        if (v0) {
            *(float2*)(H + (size_t)rg * HID + col) = make_float2(c[nt][0], c[nt][1]);
            *(float2*)(A + (size_t)rg * HID + col) =
                make_float2(c[nt][0] * rc0 + bb.x, c[nt][1] * rc0 + bb.y);
        }
        if (v8) {
            *(float2*)(H + (size_t)rg8 * HID + col) = make_float2(c[nt][2], c[nt][3]);
            *(float2*)(A + (size_t)rg8 * HID + col) =
                make_float2(c[nt][2] * rc8 + bb.x, c[nt][3] * rc8 + bb.y);
        }
    }
}

// ---------------- scatter: A[dst] += H[src] * dinv[src]*dinv[dst] ----------------
__global__ __launch_bounds__(256) void scatter_kernel(const int* __restrict__ ei,
                                                      const float* __restrict__ H,
                                                      float* __restrict__ A) {
    int gtid = blockIdx.x * blockDim.x + threadIdx.x;
    int e = gtid >> 5;
    int lane = threadIdx.x & 31;
    if (e >= N_EDGES) return;
    int is64 = g_is64;
    int s = edge_src(ei, e, is64);
    int d = edge_dst(ei, e, is64);
    float w = g_dinv[s] * g_dinv[d];
    float4 hv = ((const float4*)(H + (size_t)s * HID))[lane];
    float4 m = make_float4(hv.x * w, hv.y * w, hv.z * w, hv.w * w);
    float* dst = A + (size_t)d * HID + lane * 4;
    asm volatile("red.global.add.v4.f32 [%0], {%1,%2,%3,%4};"
                 :: "l"(dst), "f"(m.x), "f"(m.y), "f"(m.z), "f"(m.w)
                 : "memory");
}

// ---------------- final activation ----------------
__global__ void act_out_kernel(const float* __restrict__ A, float* __restrict__ out) {
    int i = blockIdx.x * blockDim.x + threadIdx.x;
    if (i >= N_NODES * HID / 4) return;
    int c4 = i & 31;
    float4 g = ((const float4*)g_gate)[c4];
    float4 v = ((const float4*)A)[i];
    v.x = fmaxf(v.x, 0.f) * g.x;
    v.y = fmaxf(v.y, 0.f) * g.y;
    v.z = fmaxf(v.z, 0.f) * g.z;
    v.w = fmaxf(v.w, 0.f) * g.w;
    ((float4*)out)[i] = v;
}

// ---------------- launch ----------------
extern "C" void kernel_launch(void* const* d_in, const int* in_sizes, int n_in,
                              void* d_out, int out_size) {
    const float* x   = (const float*)d_in[0];
    const int*   ei  = (const int*)d_in[1];
    const float* ts  = (const float*)d_in[2];
    const float* W0  = (const float*)d_in[3];
    const float* b0  = (const float*)d_in[4];
    const float* W1  = (const float*)d_in[5];
    const float* b1  = (const float*)d_in[6];
    const float* W2  = (const float*)d_in[7];
    const float* b2  = (const float*)d_in[8];
    const float* Wg1 = (const float*)d_in[9];
    const float* bg1 = (const float*)d_in[10];
    const float* Wg2 = (const float*)d_in[11];
    const float* bg2 = (const float*)d_in[12];
    float* out = (float*)d_out;

    const int SMEM = 16384 * 4 + 512;
    cudaFuncSetAttribute(gemm_mma_kernel<0>, cudaFuncAttributeMaxDynamicSharedMemorySize, SMEM);
    cudaFuncSetAttribute(gemm_mma_kernel<1>, cudaFuncAttributeMaxDynamicSharedMemorySize, SMEM);

    float *H, *A;
    uint *Wh, *Wl;
    cudaGetSymbolAddress((void**)&H,  g_H);
    cudaGetSymbolAddress((void**)&A,  g_A);
    cudaGetSymbolAddress((void**)&Wh, g_Wh);
    cudaGetSymbolAddress((void**)&Wl, g_Wl);

    // preprocessing
    detect_kernel<<<1, 256>>>(ei);
    zero_cnt_kernel<<<(N_NODES + 255) / 256, 256>>>();
    count_kernel<<<(N_EDGES + 255) / 256, 256>>>(ei);
    finalize_deg_kernel<<<(N_NODES + 255) / 256, 256>>>();
    gate_kernel<<<1, HID>>>(ts, Wg1, bg1, Wg2, bg2);
    convW_kernel<<<32, 256>>>(W0, Wh,            Wl);
    convW_kernel<<<32, 256>>>(W1, Wh + 8192,     Wl + 8192);
    convW_kernel<<<32, 256>>>(W2, Wh + 16384,    Wl + 16384);

    const int gemm_blocks = (N_NODES + 127) / 128;
    const int scat_blocks = (N_EDGES * 32 + 255) / 256;

    // layer 0
    gemm_mma_kernel<0><<<gemm_blocks, 256, SMEM>>>(x, Wh, Wl, b0, H, A);
    scatter_kernel<<<scat_blocks, 256>>>(ei, H, A);
    // layer 1 (fused relu*gate on input, in-place on A)
    gemm_mma_kernel<1><<<gemm_blocks, 256, SMEM>>>(A, Wh + 8192, Wl + 8192, b1, H, A);
    scatter_kernel<<<scat_blocks, 256>>>(ei, H, A);
    // layer 2
    gemm_mma_kernel<1><<<gemm_blocks, 256, SMEM>>>(A, Wh + 16384, Wl + 16384, b2, H, A);
    scatter_kernel<<<scat_blocks, 256>>>(ei, H, A);
    // final activation
    act_out_kernel<<<(N_NODES * HID / 4 + 255) / 256, 256>>>(A, out);
}

// round 4
// speedup vs baseline: 1.9484x; 1.5209x over previous
#include <cuda_runtime.h>
#include <cuda_bf16.h>
#include <math.h>

#define N_NODES 100000
#define N_EDGES 600000
#define HID 128
#define SCAN_BLOCKS ((N_NODES + 255) / 256)   // 391

typedef unsigned int uint;

// ---------------- device scratch (no allocs allowed) ----------------
__device__ float g_H[(size_t)N_NODES * HID];   // h = X @ W
__device__ float g_A[(size_t)N_NODES * HID];   // layer output (pre-activation)
__device__ float g_dinv[N_NODES];              // rsqrt(deg)
__device__ float g_recip[N_NODES];             // 1/deg
__device__ int   g_cnt[N_NODES];               // in-degree count
__device__ int   g_fill[N_NODES];              // CSR fill cursors
__device__ int   g_rowptr[N_NODES + 1];        // CSR row pointers (by dst)
__device__ int   g_bsum[512];                  // block sums for scan
__device__ int   g_csr_src[N_EDGES];           // CSR column indices (src)
__device__ float g_gate[HID];                  // temporal gate
__device__ int   g_is64;                       // edge_index dtype flag
__device__ uint  g_Wh[3][8192];                // W hi, fragment-packed bf16x2
__device__ uint  g_Wl[3][8192];                // W lo, fragment-packed bf16x2

// ---------------- edge-index dtype detection ----------------
__global__ void detect_kernel(const int* __restrict__ ei) {
    __shared__ int any_nz;
    if (threadIdx.x == 0) any_nz = 0;
    __syncthreads();
    int local = 0;
    for (int i = threadIdx.x; i < 4096; i += blockDim.x) local |= ei[2 * i + 1];
    if (local) atomicOr(&any_nz, 1);
    __syncthreads();
    if (threadIdx.x == 0) g_is64 = (any_nz == 0) ? 1 : 0;
}

__device__ __forceinline__ int edge_src(const int* ei, int e, int is64) {
    return is64 ? ei[2 * e] : ei[e];
}
__device__ __forceinline__ int edge_dst(const int* ei, int e, int is64) {
    return is64 ? ei[2 * (N_EDGES + e)] : ei[N_EDGES + e];
}

// ---------------- degree + CSR build ----------------
__global__ void zero_cnt_kernel() {
    int i = blockIdx.x * blockDim.x + threadIdx.x;
    if (i < N_NODES) g_cnt[i] = 0;
}

__global__ void count_kernel(const int* __restrict__ ei) {
    int e = blockIdx.x * blockDim.x + threadIdx.x;
    if (e >= N_EDGES) return;
    atomicAdd(&g_cnt[edge_dst(ei, e, g_is64)], 1);
}

__global__ void finalize_deg_kernel() {
    int i = blockIdx.x * blockDim.x + threadIdx.x;
    if (i >= N_NODES) return;
    float deg = (float)g_cnt[i] + 1.0f;
    g_dinv[i]  = rsqrtf(deg);
    g_recip[i] = 1.0f / deg;
}

// scan step 1: per-block sums of g_cnt
__global__ void scan1_kernel() {
    __shared__ int sh[256];
    int i = blockIdx.x * 256 + threadIdx.x;
    sh[threadIdx.x] = (i < N_NODES) ? g_cnt[i] : 0;
    __syncthreads();
#pragma unroll
    for (int s = 128; s > 0; s >>= 1) {
        if (threadIdx.x < s) sh[threadIdx.x] += sh[threadIdx.x + s];
        __syncthreads();
    }
    if (threadIdx.x == 0) g_bsum[blockIdx.x] = sh[0];
}

// scan step 2: exclusive scan of block sums (single block, Hillis-Steele)
__global__ void scan2_kernel() {
    __shared__ int sh[512];
    int t = threadIdx.x;
    int v = (t < SCAN_BLOCKS) ? g_bsum[t] : 0;
    sh[t] = v;
    __syncthreads();
#pragma unroll
    for (int off = 1; off < 512; off <<= 1) {
        int x = (t >= off) ? sh[t - off] : 0;
        __syncthreads();
        sh[t] += x;
        __syncthreads();
    }
    if (t < SCAN_BLOCKS) g_bsum[t] = sh[t] - v;   // exclusive
}

// scan step 3: per-block exclusive scan + offset -> rowptr; zero fill cursors
__global__ void scan3_kernel() {
    __shared__ int sh[256];
    int i = blockIdx.x * 256 + threadIdx.x;
    int v = (i < N_NODES) ? g_cnt[i] : 0;
    sh[threadIdx.x] = v;
    __syncthreads();
#pragma unroll
    for (int off = 1; off < 256; off <<= 1) {
        int x = (threadIdx.x >= off) ? sh[threadIdx.x - off] : 0;
        __syncthreads();
        sh[threadIdx.x] += x;
        __syncthreads();
    }
    if (i < N_NODES) {
        g_rowptr[i] = g_bsum[blockIdx.x] + sh[threadIdx.x] - v;
        g_fill[i] = 0;
    }
    if (i == N_NODES - 1) g_rowptr[N_NODES] = N_EDGES;
}

__global__ void fill_kernel(const int* __restrict__ ei) {
    int e = blockIdx.x * blockDim.x + threadIdx.x;
    if (e >= N_EDGES) return;
    int is64 = g_is64;
    int s = edge_src(ei, e, is64);
    int d = edge_dst(ei, e, is64);
    int pos = g_rowptr[d] + atomicAdd(&g_fill[d], 1);
    g_csr_src[pos] = s;
}

// ---------------- temporal gate ----------------
__global__ void gate_kernel(const float* __restrict__ t,
                            const float* __restrict__ Wg1, const float* __restrict__ bg1,
                            const float* __restrict__ Wg2, const float* __restrict__ bg2) {
    __shared__ float h1[HID];
    int j = threadIdx.x;
    float tv = t[0];
    h1[j] = tanhf(tv * Wg1[j] + bg1[j]);
    __syncthreads();
    float s = bg2[j];
#pragma unroll 8
    for (int k = 0; k < HID; k++) s += h1[k] * Wg2[k * HID + j];
    g_gate[j] = 1.0f / (1.0f + expf(-s));
}

// ---------------- W -> fragment-packed bf16 hi/lo ----------------
__global__ void convW_kernel(const float* __restrict__ W,
                             uint* __restrict__ Wh, uint* __restrict__ Wl) {
    int t = blockIdx.x * blockDim.x + threadIdx.x;
    if (t >= 8192) return;
    int r = t & 1, lane = (t >> 1) & 31, nt = (t >> 6) & 15, kc = t >> 10;
    int k = kc * 16 + r * 8 + (lane & 3) * 2;
    int n = nt * 8 + (lane >> 2);
    float w0 = W[k * HID + n];
    float w1 = W[(k + 1) * HID + n];
    __nv_bfloat162 h = __floats2bfloat162_rn(w0, w1);
    __nv_bfloat162 l = __floats2bfloat162_rn(w0 - __bfloat162float(h.x),
                                             w1 - __bfloat162float(h.y));
    Wh[t] = *(uint*)&h;
    Wl[t] = *(uint*)&l;
}

// ---------------- tensor-core GEMM: H = act(Xin) @ W ----------------
__device__ __forceinline__ void mma_bf16(float* c, const uint* a, const uint* b) {
    asm volatile(
        "mma.sync.aligned.m16n8k16.row.col.f32.bf16.bf16.f32 "
        "{%0,%1,%2,%3}, {%4,%5,%6,%7}, {%8,%9}, {%0,%1,%2,%3};"
        : "+f"(c[0]), "+f"(c[1]), "+f"(c[2]), "+f"(c[3])
        : "r"(a[0]), "r"(a[1]), "r"(a[2]), "r"(a[3]), "r"(b[0]), "r"(b[1]));
}

template <int ACT>
__device__ __forceinline__ void load_frag(uint& hi, uint& lo, const float* base,
                                          int k, bool valid, const float* sg) {
    float2 v = valid ? *(const float2*)(base + k) : make_float2(0.f, 0.f);
    if (ACT) {
        v.x = fmaxf(v.x, 0.f) * sg[k];
        v.y = fmaxf(v.y, 0.f) * sg[k + 1];
    }
    __nv_bfloat162 h = __floats2bfloat162_rn(v.x, v.y);
    __nv_bfloat162 l = __floats2bfloat162_rn(v.x - __bfloat162float(h.x),
                                             v.y - __bfloat162float(h.y));
    hi = *(uint*)&h;
    lo = *(uint*)&l;
}

template <int ACT>
__global__ __launch_bounds__(256) void gemm_mma_kernel(
    const float* __restrict__ Xin, const uint* __restrict__ Wh,
    const uint* __restrict__ Wl, float* __restrict__ H) {
    extern __shared__ uint smem[];
    uint* sWh = smem;                 // 8192
    uint* sWl = smem + 8192;          // 8192
    float* sg = (float*)(smem + 16384);

    int tx = threadIdx.x;
#pragma unroll
    for (int i = tx; i < 2048; i += 256) {
        ((uint4*)sWh)[i] = ((const uint4*)Wh)[i];
        ((uint4*)sWl)[i] = ((const uint4*)Wl)[i];
    }
    if (ACT && tx < HID) sg[tx] = g_gate[tx];
    __syncthreads();

    int warp = tx >> 5, lane = tx & 31;
    int gid = lane >> 2, tig = lane & 3;
    int rg  = blockIdx.x * 128 + warp * 16 + gid;
    int rg8 = rg + 8;
    bool v0 = rg < N_NODES, v8 = rg8 < N_NODES;
    const float* X0 = Xin + (size_t)rg  * HID;
    const float* X8 = Xin + (size_t)rg8 * HID;

    float c[16][4];
#pragma unroll
    for (int nt = 0; nt < 16; nt++)
#pragma unroll
        for (int r = 0; r < 4; r++) c[nt][r] = 0.f;

#pragma unroll
    for (int kc = 0; kc < 8; kc++) {
        int k0 = kc * 16 + tig * 2;
        uint ah[4], al[4];
        load_frag<ACT>(ah[0], al[0], X0, k0,     v0, sg);
        load_frag<ACT>(ah[1], al[1], X8, k0,     v8, sg);
        load_frag<ACT>(ah[2], al[2], X0, k0 + 8, v0, sg);
        load_frag<ACT>(ah[3], al[3], X8, k0 + 8, v8, sg);

        const uint* wh = sWh + (kc * 16) * 64 + lane * 2;
        const uint* wl = sWl + (kc * 16) * 64 + lane * 2;
#pragma unroll
        for (int nt = 0; nt < 16; nt++) {
            uint bh[2], bl[2];
            uint2 t0 = *(const uint2*)(wh + nt * 64);
            uint2 t1 = *(const uint2*)(wl + nt * 64);
            bh[0] = t0.x; bh[1] = t0.y;
            bl[0] = t1.x; bl[1] = t1.y;
            mma_bf16(c[nt], ah, bh);   // hi*hi
            mma_bf16(c[nt], ah, bl);   // hi*lo
            mma_bf16(c[nt], al, bh);   // lo*hi
        }
    }

#pragma unroll
    for (int nt = 0; nt < 16; nt++) {
        int col = nt * 8 + tig * 2;
        if (v0) *(float2*)(H + (size_t)rg  * HID + col) = make_float2(c[nt][0], c[nt][1]);
        if (v8) *(float2*)(H + (size_t)rg8 * HID + col) = make_float2(c[nt][2], c[nt][3]);
    }
}

// ---------------- CSR gather: A[d] = sum_in H[s]*dinv[s]*dinv[d] + H[d]*recip[d] + b ----------------
// one warp per dst node; one float4 per lane (128 floats/row). FINAL: fuse relu*gate.
template <int FINAL>
__global__ __launch_bounds__(256) void gather_kernel(const float* __restrict__ H,
                                                     const float* __restrict__ b,
                                                     float* __restrict__ A) {
    int gtid = blockIdx.x * blockDim.x + threadIdx.x;
    int d = gtid >> 5;
    int lane = threadIdx.x & 31;
    if (d >= N_NODES) return;

    int beg = g_rowptr[d];
    int end = g_rowptr[d + 1];
    float ddinv = g_dinv[d];

    // self-loop term
    float rc = g_recip[d];
    float4 hv = ((const float4*)(H + (size_t)d * HID))[lane];
    float4 acc0 = make_float4(hv.x * rc, hv.y * rc, hv.z * rc, hv.w * rc);
    float4 acc1 = make_float4(0.f, 0.f, 0.f, 0.f);

    int e = beg;
    for (; e + 1 < end; e += 2) {
        int s0 = g_csr_src[e];
        int s1 = g_csr_src[e + 1];
        float w0 = ddinv * g_dinv[s0];
        float w1 = ddinv * g_dinv[s1];
        float4 h0 = ((const float4*)(H + (size_t)s0 * HID))[lane];
        float4 h1 = ((const float4*)(H + (size_t)s1 * HID))[lane];
        acc0.x += h0.x * w0; acc0.y += h0.y * w0; acc0.z += h0.z * w0; acc0.w += h0.w * w0;
        acc1.x += h1.x * w1; acc1.y += h1.y * w1; acc1.z += h1.z * w1; acc1.w += h1.w * w1;
    }
    if (e < end) {
        int s0 = g_csr_src[e];
        float w0 = ddinv * g_dinv[s0];
        float4 h0 = ((const float4*)(H + (size_t)s0 * HID))[lane];
        acc0.x += h0.x * w0; acc0.y += h0.y * w0; acc0.z += h0.z * w0; acc0.w += h0.w * w0;
    }

    float4 bv = ((const float4*)b)[lane];
    float4 o;
    o.x = acc0.x + acc1.x + bv.x;
    o.y = acc0.y + acc1.y + bv.y;
    o.z = acc0.z + acc1.z + bv.z;
    o.w = acc0.w + acc1.w + bv.w;

    if (FINAL) {
        float4 g = ((const float4*)g_gate)[lane];
        o.x = fmaxf(o.x, 0.f) * g.x;
        o.y = fmaxf(o.y, 0.f) * g.y;
        o.z = fmaxf(o.z, 0.f) * g.z;
        o.w = fmaxf(o.w, 0.f) * g.w;
    }
    ((float4*)(A + (size_t)d * HID))[lane] = o;
}

// ---------------- launch ----------------
extern "C" void kernel_launch(void* const* d_in, const int* in_sizes, int n_in,
                              void* d_out, int out_size) {
    const float* x   = (const float*)d_in[0];
    const int*   ei  = (const int*)d_in[1];
    const float* ts  = (const float*)d_in[2];
    const float* W0  = (const float*)d_in[3];
    const float* b0  = (const float*)d_in[4];
    const float* W1  = (const float*)d_in[5];
    const float* b1  = (const float*)d_in[6];
    const float* W2  = (const float*)d_in[7];
    const float* b2  = (const float*)d_in[8];
    const float* Wg1 = (const float*)d_in[9];
    const float* bg1 = (const float*)d_in[10];
    const float* Wg2 = (const float*)d_in[11];
    const float* bg2 = (const float*)d_in[12];
    float* out = (float*)d_out;

    const int SMEM = 16384 * 4 + 512;
    cudaFuncSetAttribute(gemm_mma_kernel<0>, cudaFuncAttributeMaxDynamicSharedMemorySize, SMEM);
    cudaFuncSetAttribute(gemm_mma_kernel<1>, cudaFuncAttributeMaxDynamicSharedMemorySize, SMEM);

    float *H, *A;
    uint *Wh, *Wl;
    cudaGetSymbolAddress((void**)&H,  g_H);
    cudaGetSymbolAddress((void**)&A,  g_A);
    cudaGetSymbolAddress((void**)&Wh, g_Wh);
    cudaGetSymbolAddress((void**)&Wl, g_Wl);

    const int nblk = (N_NODES + 255) / 256;
    const int eblk = (N_EDGES + 255) / 256;

    // preprocessing: degrees, CSR, gate, weight conversion
    detect_kernel<<<1, 256>>>(ei);
    zero_cnt_kernel<<<nblk, 256>>>();
    count_kernel<<<eblk, 256>>>(ei);
    finalize_deg_kernel<<<nblk, 256>>>();
    scan1_kernel<<<SCAN_BLOCKS, 256>>>();
    scan2_kernel<<<1, 512>>>();
    scan3_kernel<<<SCAN_BLOCKS, 256>>>();
    fill_kernel<<<eblk, 256>>>(ei);
    gate_kernel<<<1, HID>>>(ts, Wg1, bg1, Wg2, bg2);
    convW_kernel<<<32, 256>>>(W0, Wh,         Wl);
    convW_kernel<<<32, 256>>>(W1, Wh + 8192,  Wl + 8192);
    convW_kernel<<<32, 256>>>(W2, Wh + 16384, Wl + 16384);

    const int gemm_blocks = (N_NODES + 127) / 128;
    const int gath_blocks = (N_NODES * 32 + 255) / 256;

    // layer 0
    gemm_mma_kernel<0><<<gemm_blocks, 256, SMEM>>>(x, Wh, Wl, H);
    gather_kernel<0><<<gath_blocks, 256>>>(H, b0, A);
    // layer 1 (fused relu*gate on input)
    gemm_mma_kernel<1><<<gemm_blocks, 256, SMEM>>>(A, Wh + 8192, Wl + 8192, H);
    gather_kernel<0><<<gath_blocks, 256>>>(H, b1, A);
    // layer 2 (final gather fuses relu*gate and writes d_out)
    gemm_mma_kernel<1><<<gemm_blocks, 256, SMEM>>>(A, Wh + 16384, Wl + 16384, H);
    gather_kernel<1><<<gath_blocks, 256>>>(H, b2, out);
}